// round 4
// baseline (speedup 1.0000x reference)
#include <cuda_runtime.h>
#include <cstdint>

// Problem constants
#define Bb   8
#define Cc   768
#define Nn   256
#define Hh   12
#define Dd   64
#define HN   3072          // Hh*Nn
#define CNsz 196608        // Cc*Nn
#define SCALE 0.125f       // D^-0.5

// Scratch (allocation-free: __device__ globals)
__device__ float g_cp[Bb * CNsz];            // proj(cross): [B, C, N]
__device__ float g_Mpart[Bb * Hh * Dd * Dd]; // per-(b,h) partial 64x64
__device__ float g_M[Bb * Dd * Dd];          // per-b 64x64
__device__ float g_U[Bb * Nn * Cc];          // reshaped attention output [B, N, C]

// ---- packed f32x2 helpers (Blackwell dual-FP32 path; PTX-only) ----
#define FMA_F32X2(d, a, b, c) \
    asm("fma.rn.f32x2 %0, %1, %2, %3;" : "=l"(d) : "l"(a), "l"(b), "l"(c))

static __device__ __forceinline__ unsigned long long splat2(float x) {
    unsigned long long r;
    unsigned u = __float_as_uint(x);
    asm("mov.b64 %0, {%1, %1};" : "=l"(r) : "r"(u));
    return r;
}

static __device__ __forceinline__ float2 unpack2(unsigned long long v) {
    unsigned lo, hi;
    asm("mov.b64 {%0, %1}, %2;" : "=r"(lo), "=r"(hi) : "l"(v));
    return make_float2(__uint_as_float(lo), __uint_as_float(hi));
}

// ============================================================================
// Kernel 1: cp[b,o,n] = sum_c W_proj[o,c] * cross[b,c,n] + b_proj[o]
// 64x64 tile, K=16 steps, 256 threads, 2x8 micro-tile in f32x2.
// ============================================================================
__global__ __launch_bounds__(256) void k_proj(
    const float* __restrict__ W, const float* __restrict__ cross,
    const float* __restrict__ bias)
{
    __shared__ float As[16][64];   // [k][o]
    __shared__ float Bs[16][64];   // [k][n]
    const int b = blockIdx.z;
    const int otile = blockIdx.y * 64;
    const int ntile = blockIdx.x * 64;
    const int tid = threadIdx.x;
    const int r = tid >> 3;        // 0..31 -> o rows r*2, r*2+1
    const int c = tid & 7;         // 0..7  -> n cols c*8 .. c*8+7

    const int alr = tid >> 2, alk = (tid & 3) * 4;    // A tile: 64(o) x 16(k)
    const int blr = tid >> 4, bln = (tid & 15) * 4;   // B tile: 16(k) x 64(n)

    unsigned long long acc[2][4];
#pragma unroll
    for (int i = 0; i < 2; i++)
#pragma unroll
        for (int j = 0; j < 4; j++) acc[i][j] = 0ull;

    const float* Ab = W + (size_t)otile * Cc;
    const float* Bp = cross + (size_t)b * CNsz + ntile;

    for (int k0 = 0; k0 < Cc; k0 += 16) {
        float4 av = *(const float4*)(Ab + (size_t)alr * Cc + k0 + alk);
        float4 bv = *(const float4*)(Bp + (size_t)(k0 + blr) * Nn + bln);
        __syncthreads();
        As[alk + 0][alr] = av.x; As[alk + 1][alr] = av.y;
        As[alk + 2][alr] = av.z; As[alk + 3][alr] = av.w;
        *(float4*)&Bs[blr][bln] = bv;
        __syncthreads();
#pragma unroll
        for (int k = 0; k < 16; k++) {
            float2 a2 = *(const float2*)&As[k][r * 2];
            const ulonglong2* bp = (const ulonglong2*)&Bs[k][c * 8];
            ulonglong2 p0 = bp[0], p1 = bp[1];
            unsigned long long s0 = splat2(a2.x), s1 = splat2(a2.y);
            FMA_F32X2(acc[0][0], s0, p0.x, acc[0][0]);
            FMA_F32X2(acc[0][1], s0, p0.y, acc[0][1]);
            FMA_F32X2(acc[0][2], s0, p1.x, acc[0][2]);
            FMA_F32X2(acc[0][3], s0, p1.y, acc[0][3]);
            FMA_F32X2(acc[1][0], s1, p0.x, acc[1][0]);
            FMA_F32X2(acc[1][1], s1, p0.y, acc[1][1]);
            FMA_F32X2(acc[1][2], s1, p1.x, acc[1][2]);
            FMA_F32X2(acc[1][3], s1, p1.y, acc[1][3]);
        }
    }

    float* outp = g_cp + (size_t)b * CNsz;
#pragma unroll
    for (int i = 0; i < 2; i++) {
        const int o = otile + r * 2 + i;
        const float bo = bias[o];
        float2 f0 = unpack2(acc[i][0]);
        float2 f1 = unpack2(acc[i][1]);
        float2 f2 = unpack2(acc[i][2]);
        float2 f3 = unpack2(acc[i][3]);
        float4* dst = (float4*)(outp + (size_t)o * Nn + ntile + c * 8);
        dst[0] = make_float4(f0.x + bo, f0.y + bo, f1.x + bo, f1.y + bo);
        dst[1] = make_float4(f2.x + bo, f2.y + bo, f3.x + bo, f3.y + bo);
    }
}

// ============================================================================
// Kernel 2a: Mpart[b,h][d,d'] = sum_n cp[b, d*H+h, n] * cross[b, d'*H+h, n]
// One block per (b,h); 64x64 output, K=256 reduction (NT), scalar 4x4 micro.
// ============================================================================
__global__ __launch_bounds__(256) void k_mpart(const float* __restrict__ cross)
{
    __shared__ float As[16][64];   // [nk][d]
    __shared__ float Bs[16][64];   // [nk][d']
    const int h = blockIdx.x;
    const int b = blockIdx.y;
    const int tid = threadIdx.x;
    const int r = tid >> 4, c = tid & 15;
    const int lr = tid >> 2, lk = (tid & 3) * 4;

    const float* Ab = g_cp + (size_t)b * CNsz + h * Nn;   // [d][n] at +d*HN+n
    const float* Bp = cross + (size_t)b * CNsz + h * Nn;  // [d'][n]

    float acc[4][4];
#pragma unroll
    for (int i = 0; i < 4; i++)
#pragma unroll
        for (int j = 0; j < 4; j++) acc[i][j] = 0.f;

    for (int k0 = 0; k0 < Nn; k0 += 16) {
        float4 av = *(const float4*)(Ab + (size_t)lr * HN + k0 + lk);
        float4 bv = *(const float4*)(Bp + (size_t)lr * HN + k0 + lk);
        __syncthreads();
        As[lk + 0][lr] = av.x; As[lk + 1][lr] = av.y;
        As[lk + 2][lr] = av.z; As[lk + 3][lr] = av.w;
        Bs[lk + 0][lr] = bv.x; Bs[lk + 1][lr] = bv.y;
        Bs[lk + 2][lr] = bv.z; Bs[lk + 3][lr] = bv.w;
        __syncthreads();
#pragma unroll
        for (int k = 0; k < 16; k++) {
            float ar[4], br[4];
            *(float4*)ar = *(const float4*)&As[k][r * 4];
            *(float4*)br = *(const float4*)&Bs[k][c * 4];
#pragma unroll
            for (int i = 0; i < 4; i++)
#pragma unroll
                for (int j = 0; j < 4; j++) acc[i][j] += ar[i] * br[j];
        }
    }

    float* mp = g_Mpart + ((size_t)b * Hh + h) * 4096;
#pragma unroll
    for (int i = 0; i < 4; i++) {
        *(float4*)(mp + (size_t)(r * 4 + i) * 64 + c * 4) =
            make_float4(acc[i][0], acc[i][1], acc[i][2], acc[i][3]);
    }
}

// ============================================================================
// Kernel 2b: M[b] = sum_h Mpart[b,h]
// ============================================================================
__global__ __launch_bounds__(256) void k_mred()
{
    const int idx = blockIdx.x * 256 + threadIdx.x;   // 8*4096 total
    const int b = idx >> 12;
    const int e = idx & 4095;
    float s = 0.f;
#pragma unroll
    for (int h = 0; h < Hh; h++)
        s += g_Mpart[((size_t)b * Hh + h) * 4096 + e];
    g_M[(size_t)b * 4096 + e] = s;
}

// ============================================================================
// Kernel 3: Out[b,m,d'] = scale * sum_d X[b,d,m] * M[b][d,d'],
//           X[b,d,m] = x_ori[b, d*H + m/256, m%256];
// stored reshaped: U[b, m/12, (m%12)*64 + d'].
// One thread per m-row (64 accumulators), M[b] staged in SMEM.
// ============================================================================
__global__ __launch_bounds__(256) void k_out(const float* __restrict__ x_ori)
{
    __shared__ float Ms[4096];
    const int b = blockIdx.x / Hh;
    const int hp = blockIdx.x % Hh;   // = m/256 for this block
    const int tid = threadIdx.x;

    {
        const float4* src = (const float4*)(g_M + (size_t)b * 4096);
        float4* dst = (float4*)Ms;
        for (int i = tid; i < 1024; i += 256) dst[i] = src[i];
    }
    __syncthreads();

    // x element for (d): x_ori[b*CN + d*HN + hp*N + tid]
    const float* xb = x_ori + (size_t)b * CNsz + hp * Nn + tid;

    float4 acc[16];
#pragma unroll
    for (int e = 0; e < 16; e++) acc[e] = make_float4(0.f, 0.f, 0.f, 0.f);

    for (int d0 = 0; d0 < 64; d0 += 8) {
        float xr[8];
#pragma unroll
        for (int i = 0; i < 8; i++) xr[i] = xb[(size_t)(d0 + i) * HN];
#pragma unroll
        for (int i = 0; i < 8; i++) {
            const float4* Mr = (const float4*)&Ms[(d0 + i) * 64];
            const float xv = xr[i];
#pragma unroll
            for (int e = 0; e < 16; e++) {
                float4 mv = Mr[e];
                acc[e].x += xv * mv.x;
                acc[e].y += xv * mv.y;
                acc[e].z += xv * mv.z;
                acc[e].w += xv * mv.w;
            }
        }
    }

    const int m = hp * Nn + tid;
    const int nf = m / Hh;
    const int hf = m - nf * Hh;
    float4* up = (float4*)(g_U + ((size_t)b * Nn + nf) * Cc + hf * Dd);
#pragma unroll
    for (int e = 0; e < 16; e++) {
        float4 v = acc[e];
        v.x *= SCALE; v.y *= SCALE; v.z *= SCALE; v.w *= SCALE;
        up[e] = v;
    }
}

// ============================================================================
// Kernel 4: res[b,o,n] = x_ori[b,o,n] + b_dep[o] + sum_k U[b,n,k]*W_dep[o,k]
// NT GEMM, same 64x64 / 2x8 f32x2 micro-kernel; fused skip + bias epilogue.
// ============================================================================
__global__ __launch_bounds__(256) void k_deproj(
    const float* __restrict__ Wdep, const float* __restrict__ bdep,
    const float* __restrict__ x_ori, float* __restrict__ out)
{
    __shared__ float As[16][64];   // [k][o]
    __shared__ float Bs[16][64];   // [k][n]
    const int b = blockIdx.z;
    const int otile = blockIdx.y * 64;
    const int ntile = blockIdx.x * 64;
    const int tid = threadIdx.x;
    const int r = tid >> 3;        // o rows r*2, r*2+1
    const int c = tid & 7;         // n cols c*8 .. c*8+7
    const int lr = tid >> 2, lk = (tid & 3) * 4;

    unsigned long long acc[2][4];
#pragma unroll
    for (int i = 0; i < 2; i++)
#pragma unroll
        for (int j = 0; j < 4; j++) acc[i][j] = 0ull;

    const float* Ab = Wdep + (size_t)otile * Cc;               // [o][k]
    const float* Ub = g_U + ((size_t)b * Nn + ntile) * Cc;     // [n][k]

    for (int k0 = 0; k0 < Cc; k0 += 16) {
        float4 av = *(const float4*)(Ab + (size_t)lr * Cc + k0 + lk);
        float4 uv = *(const float4*)(Ub + (size_t)lr * Cc + k0 + lk);
        __syncthreads();
        As[lk + 0][lr] = av.x; As[lk + 1][lr] = av.y;
        As[lk + 2][lr] = av.z; As[lk + 3][lr] = av.w;
        Bs[lk + 0][lr] = uv.x; Bs[lk + 1][lr] = uv.y;
        Bs[lk + 2][lr] = uv.z; Bs[lk + 3][lr] = uv.w;
        __syncthreads();
#pragma unroll
        for (int k = 0; k < 16; k++) {
            float2 a2 = *(const float2*)&As[k][r * 2];
            const ulonglong2* bp = (const ulonglong2*)&Bs[k][c * 8];
            ulonglong2 p0 = bp[0], p1 = bp[1];
            unsigned long long s0 = splat2(a2.x), s1 = splat2(a2.y);
            FMA_F32X2(acc[0][0], s0, p0.x, acc[0][0]);
            FMA_F32X2(acc[0][1], s0, p0.y, acc[0][1]);
            FMA_F32X2(acc[0][2], s0, p1.x, acc[0][2]);
            FMA_F32X2(acc[0][3], s0, p1.y, acc[0][3]);
            FMA_F32X2(acc[1][0], s1, p0.x, acc[1][0]);
            FMA_F32X2(acc[1][1], s1, p0.y, acc[1][1]);
            FMA_F32X2(acc[1][2], s1, p1.x, acc[1][2]);
            FMA_F32X2(acc[1][3], s1, p1.y, acc[1][3]);
        }
    }

#pragma unroll
    for (int i = 0; i < 2; i++) {
        const int o = otile + r * 2 + i;
        const float bo = bdep[o];
        const size_t base = (size_t)b * CNsz + (size_t)o * Nn + ntile + c * 8;
        float4 x0 = *(const float4*)(x_ori + base);
        float4 x1 = *(const float4*)(x_ori + base + 4);
        float2 f0 = unpack2(acc[i][0]);
        float2 f1 = unpack2(acc[i][1]);
        float2 f2 = unpack2(acc[i][2]);
        float2 f3 = unpack2(acc[i][3]);
        float4 v0 = make_float4(f0.x + bo + x0.x, f0.y + bo + x0.y,
                                f1.x + bo + x0.z, f1.y + bo + x0.w);
        float4 v1 = make_float4(f2.x + bo + x1.x, f2.y + bo + x1.y,
                                f3.x + bo + x1.z, f3.y + bo + x1.w);
        *(float4*)(out + base) = v0;
        *(float4*)(out + base + 4) = v1;
    }
}

// ============================================================================
// Launch
// ============================================================================
extern "C" void kernel_launch(void* const* d_in, const int* in_sizes, int n_in,
                              void* d_out, int out_size)
{
    (void)in_sizes; (void)n_in; (void)out_size;
    const float* x_ori  = (const float*)d_in[0];
    const float* cross  = (const float*)d_in[1];
    const float* W_proj = (const float*)d_in[2];
    const float* b_proj = (const float*)d_in[3];
    const float* W_dep  = (const float*)d_in[4];
    const float* b_dep  = (const float*)d_in[5];
    float* out = (float*)d_out;

    // 1) cp = W_proj @ cross  (per batch; grid: n-tiles x o-tiles x B)
    k_proj<<<dim3(Nn / 64, Cc / 64, Bb), 256>>>(W_proj, cross, b_proj);
    // 2) per-(b,h) partial 64x64 Gram-like matrices, then reduce over h
    k_mpart<<<dim3(Hh, Bb), 256>>>(cross);
    k_mred<<<(Bb * Dd * Dd) / 256, 256>>>();
    // 3) apply M to x (64-K batched matvec rows), reshape into U
    k_out<<<Bb * Hh, 256>>>(x_ori);
    // 4) deproj GEMM + bias + skip, transposed write
    k_deproj<<<dim3(Nn / 64, Cc / 64, Bb), 256>>>(W_dep, b_dep, x_ori, out);
}

// round 5
// speedup vs baseline: 2.1487x; 2.1487x over previous
#include <cuda_runtime.h>
#include <cstdint>

// Problem constants
#define Bb   8
#define Cc   768
#define Nn   256
#define Hh   12
#define Dd   64
#define HN   3072          // Hh*Nn
#define CNsz 196608        // Cc*Nn
#define SCALE 0.125f       // D^-0.5

// GEMM tiling
#define BM   96
#define BN   128
#define BK   32
#define NT   (Cc / BK)     // 24 k-tiles
#define PAD_A 100          // As row stride (96 + 4): kills STS bank conflicts, keeps 8B align

// Scratch (allocation-free: __device__ globals)
__device__ float g_cp[Bb * CNsz];            // proj(cross): [B, C, N]
__device__ float g_Mpart[Bb * Hh * Dd * Dd]; // per-(b,h) partial 64x64
__device__ float g_M[Bb * Dd * Dd];          // per-b 64x64
__device__ float g_U[Bb * Nn * Cc];          // attention output, [B, N, C]

// ---- packed f32x2 helpers (Blackwell dual-FP32 path; PTX-only) ----
#define FMA_F32X2(d, a, b, c) \
    asm("fma.rn.f32x2 %0, %1, %2, %3;" : "=l"(d) : "l"(a), "l"(b), "l"(c))

static __device__ __forceinline__ unsigned long long splat2(float x) {
    unsigned long long r;
    unsigned u = __float_as_uint(x);
    asm("mov.b64 %0, {%1, %1};" : "=l"(r) : "r"(u));
    return r;
}

static __device__ __forceinline__ float2 unpack2(unsigned long long v) {
    unsigned lo, hi;
    asm("mov.b64 {%0, %1}, %2;" : "=r"(lo), "=r"(hi) : "l"(v));
    return make_float2(__uint_as_float(lo), __uint_as_float(hi));
}

// 6x8 f32x2 micro-kernel over one BK tile in smem
#define MICRO_COMPUTE(As_, Bs_)                                               \
    _Pragma("unroll")                                                         \
    for (int k = 0; k < BK; k++) {                                            \
        float2 a01 = *(const float2*)&As_[k][ty6];                            \
        float2 a23 = *(const float2*)&As_[k][ty6 + 2];                        \
        float2 a45 = *(const float2*)&As_[k][ty6 + 4];                        \
        ulonglong2 p0 = *(const ulonglong2*)&Bs_[k][tx8];                     \
        ulonglong2 p1 = *(const ulonglong2*)&Bs_[k][tx8 + 4];                 \
        unsigned long long s;                                                 \
        s = splat2(a01.x);                                                    \
        FMA_F32X2(acc[0][0], s, p0.x, acc[0][0]);                             \
        FMA_F32X2(acc[0][1], s, p0.y, acc[0][1]);                             \
        FMA_F32X2(acc[0][2], s, p1.x, acc[0][2]);                             \
        FMA_F32X2(acc[0][3], s, p1.y, acc[0][3]);                             \
        s = splat2(a01.y);                                                    \
        FMA_F32X2(acc[1][0], s, p0.x, acc[1][0]);                             \
        FMA_F32X2(acc[1][1], s, p0.y, acc[1][1]);                             \
        FMA_F32X2(acc[1][2], s, p1.x, acc[1][2]);                             \
        FMA_F32X2(acc[1][3], s, p1.y, acc[1][3]);                             \
        s = splat2(a23.x);                                                    \
        FMA_F32X2(acc[2][0], s, p0.x, acc[2][0]);                             \
        FMA_F32X2(acc[2][1], s, p0.y, acc[2][1]);                             \
        FMA_F32X2(acc[2][2], s, p1.x, acc[2][2]);                             \
        FMA_F32X2(acc[2][3], s, p1.y, acc[2][3]);                             \
        s = splat2(a23.y);                                                    \
        FMA_F32X2(acc[3][0], s, p0.x, acc[3][0]);                             \
        FMA_F32X2(acc[3][1], s, p0.y, acc[3][1]);                             \
        FMA_F32X2(acc[3][2], s, p1.x, acc[3][2]);                             \
        FMA_F32X2(acc[3][3], s, p1.y, acc[3][3]);                             \
        s = splat2(a45.x);                                                    \
        FMA_F32X2(acc[4][0], s, p0.x, acc[4][0]);                             \
        FMA_F32X2(acc[4][1], s, p0.y, acc[4][1]);                             \
        FMA_F32X2(acc[4][2], s, p1.x, acc[4][2]);                             \
        FMA_F32X2(acc[4][3], s, p1.y, acc[4][3]);                             \
        s = splat2(a45.y);                                                    \
        FMA_F32X2(acc[5][0], s, p0.x, acc[5][0]);                             \
        FMA_F32X2(acc[5][1], s, p0.y, acc[5][1]);                             \
        FMA_F32X2(acc[5][2], s, p1.x, acc[5][2]);                             \
        FMA_F32X2(acc[5][3], s, p1.y, acc[5][3]);                             \
    }

// ============================================================================
// Kernel 1: cp[b,o,n] = sum_c W_proj[o,c] * cross[b,c,n] + b_proj[o]
// BM=96 x BN=128 x BK=32, 256 threads, 6x8 f32x2 micro-tile, reg-staged
// prefetch, 2 barriers per 32-k tile. Grid = 16 n-tiles x 8 o-tiles = 128.
// ============================================================================
__global__ __launch_bounds__(256) void k_proj(
    const float* __restrict__ W, const float* __restrict__ cross,
    const float* __restrict__ bias)
{
    __shared__ float As[BK][PAD_A];   // [k][o]
    __shared__ float Bs[BK][BN];      // [k][n]
    const int tid = threadIdx.x;
    const int otile = blockIdx.y * BM;
    const int gnt = blockIdx.x;               // 0..15 over (b, half)
    const int b = gnt >> 1;
    const int noff = (gnt & 1) * BN;

    const int ty6 = (tid >> 4) * 6;
    const int tx8 = (tid & 15) * 8;

    // A loader: 3 rows (ar0, +32, +64), 4 k-cols at ak
    const int ar0 = tid >> 3;
    const int ak = (tid & 7) * 4;
    // B loader: 2 k-rows (kr, +16), 8 n at bn
    const int kr = tid >> 4;
    const int bn = (tid & 15) * 8;

    const float* Ag = W + (size_t)(otile + ar0) * Cc + ak;
    const float* Bg = cross + (size_t)b * CNsz + (size_t)kr * Nn + noff + bn;

    unsigned long long acc[6][4];
#pragma unroll
    for (int i = 0; i < 6; i++)
#pragma unroll
        for (int j = 0; j < 4; j++) acc[i][j] = 0ull;

    float4 as[3], bs0, bs1, bs2, bs3;
    as[0] = *(const float4*)(Ag);
    as[1] = *(const float4*)(Ag + (size_t)32 * Cc);
    as[2] = *(const float4*)(Ag + (size_t)64 * Cc);
    bs0 = *(const float4*)(Bg);
    bs1 = *(const float4*)(Bg + 4);
    bs2 = *(const float4*)(Bg + (size_t)16 * Nn);
    bs3 = *(const float4*)(Bg + (size_t)16 * Nn + 4);

#pragma unroll
    for (int g = 0; g < 3; g++) {
        const int row = ar0 + g * 32;
        As[ak + 0][row] = as[g].x; As[ak + 1][row] = as[g].y;
        As[ak + 2][row] = as[g].z; As[ak + 3][row] = as[g].w;
    }
    *(float4*)&Bs[kr][bn] = bs0;
    *(float4*)&Bs[kr][bn + 4] = bs1;
    *(float4*)&Bs[kr + 16][bn] = bs2;
    *(float4*)&Bs[kr + 16][bn + 4] = bs3;
    __syncthreads();

    for (int kt = 0; kt < NT; kt++) {
        if (kt + 1 < NT) {
            Ag += BK;
            Bg += (size_t)BK * Nn;
            as[0] = *(const float4*)(Ag);
            as[1] = *(const float4*)(Ag + (size_t)32 * Cc);
            as[2] = *(const float4*)(Ag + (size_t)64 * Cc);
            bs0 = *(const float4*)(Bg);
            bs1 = *(const float4*)(Bg + 4);
            bs2 = *(const float4*)(Bg + (size_t)16 * Nn);
            bs3 = *(const float4*)(Bg + (size_t)16 * Nn + 4);
        }
        MICRO_COMPUTE(As, Bs)
        if (kt + 1 < NT) {
            __syncthreads();
#pragma unroll
            for (int g = 0; g < 3; g++) {
                const int row = ar0 + g * 32;
                As[ak + 0][row] = as[g].x; As[ak + 1][row] = as[g].y;
                As[ak + 2][row] = as[g].z; As[ak + 3][row] = as[g].w;
            }
            *(float4*)&Bs[kr][bn] = bs0;
            *(float4*)&Bs[kr][bn + 4] = bs1;
            *(float4*)&Bs[kr + 16][bn] = bs2;
            *(float4*)&Bs[kr + 16][bn + 4] = bs3;
            __syncthreads();
        }
    }

    float* outp = g_cp + (size_t)b * CNsz + noff + tx8;
#pragma unroll
    for (int i = 0; i < 6; i++) {
        const int o = otile + ty6 + i;
        const float bo = bias[o];
        float2 f0 = unpack2(acc[i][0]);
        float2 f1 = unpack2(acc[i][1]);
        float2 f2 = unpack2(acc[i][2]);
        float2 f3 = unpack2(acc[i][3]);
        float4* dst = (float4*)(outp + (size_t)o * Nn);
        dst[0] = make_float4(f0.x + bo, f0.y + bo, f1.x + bo, f1.y + bo);
        dst[1] = make_float4(f2.x + bo, f2.y + bo, f3.x + bo, f3.y + bo);
    }
}

// ============================================================================
// Kernel 2a: Mpart[b,h][d,d'] = sum_n cp[b, d*H+h, n] * cross[b, d'*H+h, n]
// One block per (b,h); 64x64 output, K=256 (NT), 4x4 micro in f32x2.
// ============================================================================
__global__ __launch_bounds__(256) void k_mpart(const float* __restrict__ cross)
{
    __shared__ float As[16][64];   // [nk][d]
    __shared__ float Bs[16][64];   // [nk][d']
    const int h = blockIdx.x;
    const int b = blockIdx.y;
    const int tid = threadIdx.x;
    const int r = tid >> 4, c = tid & 15;
    const int lr = tid >> 2, lk = (tid & 3) * 4;

    const float* Ab = g_cp + (size_t)b * CNsz + h * Nn;   // [d][n] at +d*HN+n
    const float* Bp = cross + (size_t)b * CNsz + h * Nn;  // [d'][n]

    unsigned long long acc[4][2];
#pragma unroll
    for (int i = 0; i < 4; i++) { acc[i][0] = 0ull; acc[i][1] = 0ull; }

    for (int k0 = 0; k0 < Nn; k0 += 16) {
        float4 av = *(const float4*)(Ab + (size_t)lr * HN + k0 + lk);
        float4 bv = *(const float4*)(Bp + (size_t)lr * HN + k0 + lk);
        __syncthreads();
        As[lk + 0][lr] = av.x; As[lk + 1][lr] = av.y;
        As[lk + 2][lr] = av.z; As[lk + 3][lr] = av.w;
        Bs[lk + 0][lr] = bv.x; Bs[lk + 1][lr] = bv.y;
        Bs[lk + 2][lr] = bv.z; Bs[lk + 3][lr] = bv.w;
        __syncthreads();
#pragma unroll
        for (int k = 0; k < 16; k++) {
            float4 ar = *(const float4*)&As[k][r * 4];
            ulonglong2 bp = *(const ulonglong2*)&Bs[k][c * 4];
            unsigned long long s;
            s = splat2(ar.x);
            FMA_F32X2(acc[0][0], s, bp.x, acc[0][0]);
            FMA_F32X2(acc[0][1], s, bp.y, acc[0][1]);
            s = splat2(ar.y);
            FMA_F32X2(acc[1][0], s, bp.x, acc[1][0]);
            FMA_F32X2(acc[1][1], s, bp.y, acc[1][1]);
            s = splat2(ar.z);
            FMA_F32X2(acc[2][0], s, bp.x, acc[2][0]);
            FMA_F32X2(acc[2][1], s, bp.y, acc[2][1]);
            s = splat2(ar.w);
            FMA_F32X2(acc[3][0], s, bp.x, acc[3][0]);
            FMA_F32X2(acc[3][1], s, bp.y, acc[3][1]);
        }
    }

    float* mp = g_Mpart + ((size_t)b * Hh + h) * 4096;
#pragma unroll
    for (int i = 0; i < 4; i++) {
        float2 lo = unpack2(acc[i][0]);
        float2 hi = unpack2(acc[i][1]);
        *(float4*)(mp + (size_t)(r * 4 + i) * 64 + c * 4) =
            make_float4(lo.x, lo.y, hi.x, hi.y);
    }
}

// ============================================================================
// Kernel 2b: M[b] = sum_h Mpart[b,h]
// ============================================================================
__global__ __launch_bounds__(256) void k_mred()
{
    const int idx = blockIdx.x * 256 + threadIdx.x;   // 8*4096 total
    const int b = idx >> 12;
    const int e = idx & 4095;
    float s = 0.f;
#pragma unroll
    for (int h = 0; h < Hh; h++)
        s += g_Mpart[((size_t)b * Hh + h) * 4096 + e];
    g_M[(size_t)b * 4096 + e] = s;
}

// ============================================================================
// Kernel 3: Out[b,m,d'] = scale * sum_d X[b,d,m] * M[b][d,d'],
//           X[b,d,m] = x_ori[b, d*H + m/256, m%256]; U[b, m/12, (m%12)*64+d'].
// Split d' in halves (blockIdx.y): 32 accums/thread, grid 96x2.
// ============================================================================
__global__ __launch_bounds__(256) void k_out(const float* __restrict__ x_ori)
{
    __shared__ float Ms[64][32];
    const int b = blockIdx.x / Hh;
    const int hp = blockIdx.x % Hh;   // = m/256 for this block
    const int half = blockIdx.y;      // d' half
    const int tid = threadIdx.x;

    for (int idx = tid; idx < 512; idx += 256) {
        const int d = idx >> 3, c4 = (idx & 7) * 4;
        *(float4*)&Ms[d][c4] =
            *(const float4*)(g_M + (size_t)b * 4096 + d * 64 + half * 32 + c4);
    }
    __syncthreads();

    const float* xb = x_ori + (size_t)b * CNsz + hp * Nn + tid;

    float4 acc[8];
#pragma unroll
    for (int e = 0; e < 8; e++) acc[e] = make_float4(0.f, 0.f, 0.f, 0.f);

    for (int d0 = 0; d0 < 64; d0 += 8) {
        float xr[8];
#pragma unroll
        for (int i = 0; i < 8; i++) xr[i] = xb[(size_t)(d0 + i) * HN];
#pragma unroll
        for (int i = 0; i < 8; i++) {
            const float4* Mr = (const float4*)&Ms[d0 + i][0];
            const float xv = xr[i];
#pragma unroll
            for (int e = 0; e < 8; e++) {
                float4 mv = Mr[e];
                acc[e].x += xv * mv.x;
                acc[e].y += xv * mv.y;
                acc[e].z += xv * mv.z;
                acc[e].w += xv * mv.w;
            }
        }
    }

    const int m = hp * Nn + tid;
    const int nf = m / Hh;
    const int hf = m - nf * Hh;
    float4* up = (float4*)(g_U + ((size_t)b * Nn + nf) * Cc + hf * Dd + half * 32);
#pragma unroll
    for (int e = 0; e < 8; e++) {
        float4 v = acc[e];
        v.x *= SCALE; v.y *= SCALE; v.z *= SCALE; v.w *= SCALE;
        up[e] = v;
    }
}

// ============================================================================
// Kernel 4: res[b,o,n] = x_ori[b,o,n] + b_dep[o] + sum_k U[b,n,k]*W_dep[o,k]
// Same BM=96 x BN=128 x BK=32 skeleton; B tile transposed on store.
// ============================================================================
__global__ __launch_bounds__(256) void k_deproj(
    const float* __restrict__ Wdep, const float* __restrict__ bdep,
    const float* __restrict__ x_ori, float* __restrict__ out)
{
    __shared__ float As[BK][PAD_A];   // [k][o]
    __shared__ float Bs[BK][BN];      // [k][n]
    const int tid = threadIdx.x;
    const int otile = blockIdx.y * BM;
    const int gnt = blockIdx.x;
    const int b = gnt >> 1;
    const int noff = (gnt & 1) * BN;

    const int ty6 = (tid >> 4) * 6;
    const int tx8 = (tid & 15) * 8;

    const int ar0 = tid >> 3;
    const int ak = (tid & 7) * 4;
    // B loader: row (n) = tid>>1, k offset = (tid&1)*16, 16 consecutive k
    const int ur = tid >> 1;
    const int uk = (tid & 1) * 16;

    const float* Ag = Wdep + (size_t)(otile + ar0) * Cc + ak;
    const float* Ug = g_U + ((size_t)b * Nn + noff + ur) * Cc + uk;

    unsigned long long acc[6][4];
#pragma unroll
    for (int i = 0; i < 6; i++)
#pragma unroll
        for (int j = 0; j < 4; j++) acc[i][j] = 0ull;

    float4 as[3], us[4];
    as[0] = *(const float4*)(Ag);
    as[1] = *(const float4*)(Ag + (size_t)32 * Cc);
    as[2] = *(const float4*)(Ag + (size_t)64 * Cc);
#pragma unroll
    for (int j = 0; j < 4; j++) us[j] = *(const float4*)(Ug + j * 4);

#pragma unroll
    for (int g = 0; g < 3; g++) {
        const int row = ar0 + g * 32;
        As[ak + 0][row] = as[g].x; As[ak + 1][row] = as[g].y;
        As[ak + 2][row] = as[g].z; As[ak + 3][row] = as[g].w;
    }
    {
        const float* uf = (const float*)us;
#pragma unroll
        for (int j = 0; j < 16; j++) Bs[uk + j][ur] = uf[j];
    }
    __syncthreads();

    for (int kt = 0; kt < NT; kt++) {
        if (kt + 1 < NT) {
            Ag += BK;
            Ug += BK;
            as[0] = *(const float4*)(Ag);
            as[1] = *(const float4*)(Ag + (size_t)32 * Cc);
            as[2] = *(const float4*)(Ag + (size_t)64 * Cc);
#pragma unroll
            for (int j = 0; j < 4; j++) us[j] = *(const float4*)(Ug + j * 4);
        }
        MICRO_COMPUTE(As, Bs)
        if (kt + 1 < NT) {
            __syncthreads();
#pragma unroll
            for (int g = 0; g < 3; g++) {
                const int row = ar0 + g * 32;
                As[ak + 0][row] = as[g].x; As[ak + 1][row] = as[g].y;
                As[ak + 2][row] = as[g].z; As[ak + 3][row] = as[g].w;
            }
            const float* uf = (const float*)us;
#pragma unroll
            for (int j = 0; j < 16; j++) Bs[uk + j][ur] = uf[j];
            __syncthreads();
        }
    }

#pragma unroll
    for (int i = 0; i < 6; i++) {
        const int o = otile + ty6 + i;
        const float bo = bdep[o];
        const size_t base = (size_t)b * CNsz + (size_t)o * Nn + noff + tx8;
        float4 x0 = *(const float4*)(x_ori + base);
        float4 x1 = *(const float4*)(x_ori + base + 4);
        float2 f0 = unpack2(acc[i][0]);
        float2 f1 = unpack2(acc[i][1]);
        float2 f2 = unpack2(acc[i][2]);
        float2 f3 = unpack2(acc[i][3]);
        *(float4*)(out + base) = make_float4(f0.x + bo + x0.x, f0.y + bo + x0.y,
                                             f1.x + bo + x0.z, f1.y + bo + x0.w);
        *(float4*)(out + base + 4) = make_float4(f2.x + bo + x1.x, f2.y + bo + x1.y,
                                                 f3.x + bo + x1.z, f3.y + bo + x1.w);
    }
}

// ============================================================================
// Launch
// ============================================================================
extern "C" void kernel_launch(void* const* d_in, const int* in_sizes, int n_in,
                              void* d_out, int out_size)
{
    (void)in_sizes; (void)n_in; (void)out_size;
    const float* x_ori  = (const float*)d_in[0];
    const float* cross  = (const float*)d_in[1];
    const float* W_proj = (const float*)d_in[2];
    const float* b_proj = (const float*)d_in[3];
    const float* W_dep  = (const float*)d_in[4];
    const float* b_dep  = (const float*)d_in[5];
    float* out = (float*)d_out;

    // 1) cp = W_proj @ cross  (16 n-tiles over (b, half) x 8 o-tiles = 128 blocks)
    k_proj<<<dim3(16, 8), 256>>>(W_proj, cross, b_proj);
    // 2) per-(b,h) partial 64x64 matrices, then reduce over h
    k_mpart<<<dim3(Hh, Bb), 256>>>(cross);
    k_mred<<<(Bb * Dd * Dd) / 256, 256>>>();
    // 3) apply M to x, reshape into U (split d' halves)
    k_out<<<dim3(Bb * Hh, 2), 256>>>(x_ori);
    // 4) deproj GEMM + bias + skip
    k_deproj<<<dim3(16, 8), 256>>>(W_dep, b_dep, x_ori, out);
}

// round 6
// speedup vs baseline: 3.7507x; 1.7456x over previous
#include <cuda_runtime.h>
#include <cuda_bf16.h>
#include <cstdint>

// Problem constants
#define Bb   8
#define Cc   768
#define Nn   256
#define Hh   12
#define Dd   64
#define HN   3072          // Hh*Nn
#define CNsz 196608        // Cc*Nn
#define SCALE 0.125f       // D^-0.5
#define GNT  24            // K tiles of 32 (K = 768)

// Scratch (allocation-free: __device__ globals)
__device__ float g_cp[Bb * CNsz];                 // proj(cross): [B, C, N] fp32
__device__ float g_Mpart[Bb * Hh * Dd * Dd];      // per-(b,h) partial 64x64
__device__ __nv_bfloat16 g_Uhi[Bb * Nn * Cc];     // U hi plane [B, N, C]
__device__ __nv_bfloat16 g_Ulo[Bb * Nn * Cc];     // U lo plane [B, N, C]

// ---- packed f32x2 helpers (for k_mpart) ----
#define FMA_F32X2(d, a, b, c) \
    asm("fma.rn.f32x2 %0, %1, %2, %3;" : "=l"(d) : "l"(a), "l"(b), "l"(c))

static __device__ __forceinline__ unsigned long long splat2(float x) {
    unsigned long long r;
    unsigned u = __float_as_uint(x);
    asm("mov.b64 %0, {%1, %1};" : "=l"(r) : "r"(u));
    return r;
}
static __device__ __forceinline__ float2 unpack2(unsigned long long v) {
    unsigned lo, hi;
    asm("mov.b64 {%0, %1}, %2;" : "=r"(lo), "=r"(hi) : "l"(v));
    return make_float2(__uint_as_float(lo), __uint_as_float(hi));
}

// ---- tensor-core primitives ----
static __device__ __forceinline__ uint32_t smem_u32(const void* p) {
    return (uint32_t)__cvta_generic_to_shared(p);
}

#define LDSM_X4(r0, r1, r2, r3, addr) \
    asm volatile("ldmatrix.sync.aligned.m8n8.x4.shared.b16 {%0,%1,%2,%3}, [%4];" \
        : "=r"(r0), "=r"(r1), "=r"(r2), "=r"(r3) : "r"(addr))

#define LDSM_X4_T(r0, r1, r2, r3, addr) \
    asm volatile("ldmatrix.sync.aligned.m8n8.x4.trans.shared.b16 {%0,%1,%2,%3}, [%4];" \
        : "=r"(r0), "=r"(r1), "=r"(r2), "=r"(r3) : "r"(addr))

#define MMA_BF16(D, a0, a1, a2, a3, b0, b1) \
    asm volatile("mma.sync.aligned.m16n8k16.row.col.f32.bf16.bf16.f32 " \
        "{%0,%1,%2,%3}, {%4,%5,%6,%7}, {%8,%9}, {%0,%1,%2,%3};" \
        : "+f"((D)[0]), "+f"((D)[1]), "+f"((D)[2]), "+f"((D)[3]) \
        : "r"(a0), "r"(a1), "r"(a2), "r"(a3), "r"(b0), "r"(b1))

// Split 8 fp32 -> bf16 hi chunk (16B) + bf16 lo chunk (16B)
static __device__ __forceinline__ void split8(float4 u, float4 v, uint4& hi, uint4& lo) {
    float f[8] = {u.x, u.y, u.z, u.w, v.x, v.y, v.z, v.w};
    uint32_t hw[4], lw[4];
#pragma unroll
    for (int i = 0; i < 4; i++) {
        __nv_bfloat16 h0 = __float2bfloat16(f[2 * i]);
        __nv_bfloat16 h1 = __float2bfloat16(f[2 * i + 1]);
        __nv_bfloat16 l0 = __float2bfloat16(f[2 * i] - __bfloat162float(h0));
        __nv_bfloat16 l1 = __float2bfloat16(f[2 * i + 1] - __bfloat162float(h1));
        __nv_bfloat162 hh(h0, h1), ll(l0, l1);
        hw[i] = *reinterpret_cast<uint32_t*>(&hh);
        lw[i] = *reinterpret_cast<uint32_t*>(&ll);
    }
    hi = make_uint4(hw[0], hw[1], hw[2], hw[3]);
    lo = make_uint4(lw[0], lw[1], lw[2], lw[3]);
}

// Stage A tile row: m-major [128][8 chunks], chunks 0-3 hi(k0-31), 4-7 lo; XOR swizzle by m&7
static __device__ __forceinline__ void stage_A(uint4* As4, int am, int akh, const float4 a[4]) {
    const int c0 = akh >> 3;        // 0 or 2
    const int m7 = am & 7;
    uint4 h0, l0, h1, l1;
    split8(a[0], a[1], h0, l0);
    split8(a[2], a[3], h1, l1);
    uint4* row = As4 + am * 8;
    row[(c0 + 0) ^ m7] = h0;
    row[(c0 + 1) ^ m7] = h1;
    row[(c0 + 4) ^ m7] = l0;
    row[(c0 + 5) ^ m7] = l1;
}

// ============================================================================
// Kernel 1: cp = W_proj @ cross + b_proj  (per batch), bf16 3-split tensor core
// Block 128(o) x 128(n) x K=768, BK=32, 8 warps of 32x64. Grid (16, 6).
// ============================================================================
__global__ __launch_bounds__(256) void k_proj_mma(
    const float* __restrict__ W, const float* __restrict__ cross,
    const float* __restrict__ bias)
{
    __shared__ uint4 As4[128][8];   // [m][chunk]; 0-3 hi, 4-7 lo, swizzled
    __shared__ uint4 Bs4[64][16];   // [k (0-31 hi, 32-63 lo)][n chunk], swizzled
    const int tid = threadIdx.x;
    const int wid = tid >> 5, lane = tid & 31;
    const int b = blockIdx.x >> 1;
    const int noff = (blockIdx.x & 1) * 128;
    const int otile = blockIdx.y * 128;

    const int wm = (wid >> 1) * 32;
    const int wn = (wid & 1) * 64;
    const int l7 = lane & 7, l15 = lane & 15, lsel = lane >> 4;
    const int g = lane >> 2, tc = lane & 3;

    // staging indices
    const int am = tid >> 1, akh = (tid & 1) * 16;
    const int bk = tid >> 3, bj = (tid & 7) * 16;

    const float* Agp = W + (size_t)(otile + am) * Cc + akh;
    const float* Bgp = cross + (size_t)b * CNsz + (size_t)bk * Nn + noff + bj;

    const uint32_t as_base = smem_u32(&As4[0][0]);
    const uint32_t bs_base = smem_u32(&Bs4[0][0]);
    const int rowA = wm + l15;

    float acc[2][8][4];
#pragma unroll
    for (int i = 0; i < 2; i++)
#pragma unroll
        for (int j = 0; j < 8; j++)
#pragma unroll
            for (int e = 0; e < 4; e++) acc[i][j][e] = 0.f;

    float4 pa[4], pb[4];
#pragma unroll
    for (int i = 0; i < 4; i++) {
        pa[i] = *(const float4*)(Agp + i * 4);
        pb[i] = *(const float4*)(Bgp + i * 4);
    }
    // initial stage
    stage_A(&As4[0][0], am, akh, pa);
    {
        const int c0 = bj >> 3, k7 = bk & 7;
        uint4 h0, l0, h1, l1;
        split8(pb[0], pb[1], h0, l0);
        split8(pb[2], pb[3], h1, l1);
        const int p0 = (c0 & 8) | ((c0 ^ k7) & 7);
        const int p1 = ((c0 + 1) & 8) | (((c0 + 1) ^ k7) & 7);
        Bs4[bk][p0] = h0; Bs4[bk][p1] = h1;
        Bs4[bk + 32][p0] = l0; Bs4[bk + 32][p1] = l1;
    }
    __syncthreads();

    for (int kt = 0; kt < GNT; kt++) {
        if (kt + 1 < GNT) {
            Agp += 32;
            Bgp += (size_t)32 * Nn;
#pragma unroll
            for (int i = 0; i < 4; i++) {
                pa[i] = *(const float4*)(Agp + i * 4);
                pb[i] = *(const float4*)(Bgp + i * 4);
            }
        }
        // compute: 2 k16 steps
#pragma unroll
        for (int ks = 0; ks < 2; ks++) {
            const int k0 = ks * 16;
            uint32_t a_h[2][4], a_l[2][4];
#pragma unroll
            for (int mf = 0; mf < 2; mf++) {
                const uint32_t rbase = as_base + (uint32_t)(rowA + mf * 16) * 128;
                const int ch = ((k0 >> 3) + lsel) ^ l7;
                const int cl = ((k0 >> 3) + lsel + 4) ^ l7;
                LDSM_X4(a_h[mf][0], a_h[mf][1], a_h[mf][2], a_h[mf][3], rbase + ch * 16);
                LDSM_X4(a_l[mf][0], a_l[mf][1], a_l[mf][2], a_l[mf][3], rbase + cl * 16);
            }
#pragma unroll
            for (int np = 0; np < 4; np++) {
                const int c = (wn >> 3) + np * 2 + lsel;
                const int p = (c & 8) | ((c ^ l7) & 7);
                const uint32_t rb = bs_base + (uint32_t)(k0 + l15) * 256 + p * 16;
                uint32_t bh[4], bl[4];
                LDSM_X4_T(bh[0], bh[1], bh[2], bh[3], rb);
                LDSM_X4_T(bl[0], bl[1], bl[2], bl[3], rb + 32 * 256);
#pragma unroll
                for (int mf = 0; mf < 2; mf++) {
                    MMA_BF16(acc[mf][2 * np], a_h[mf][0], a_h[mf][1], a_h[mf][2], a_h[mf][3], bh[0], bh[1]);
                    MMA_BF16(acc[mf][2 * np], a_l[mf][0], a_l[mf][1], a_l[mf][2], a_l[mf][3], bh[0], bh[1]);
                    MMA_BF16(acc[mf][2 * np], a_h[mf][0], a_h[mf][1], a_h[mf][2], a_h[mf][3], bl[0], bl[1]);
                    MMA_BF16(acc[mf][2 * np + 1], a_h[mf][0], a_h[mf][1], a_h[mf][2], a_h[mf][3], bh[2], bh[3]);
                    MMA_BF16(acc[mf][2 * np + 1], a_l[mf][0], a_l[mf][1], a_l[mf][2], a_l[mf][3], bh[2], bh[3]);
                    MMA_BF16(acc[mf][2 * np + 1], a_h[mf][0], a_h[mf][1], a_h[mf][2], a_h[mf][3], bl[2], bl[3]);
                }
            }
        }
        if (kt + 1 < GNT) {
            __syncthreads();
            stage_A(&As4[0][0], am, akh, pa);
            {
                const int c0 = bj >> 3, k7 = bk & 7;
                uint4 h0, l0, h1, l1;
                split8(pb[0], pb[1], h0, l0);
                split8(pb[2], pb[3], h1, l1);
                const int p0 = (c0 & 8) | ((c0 ^ k7) & 7);
                const int p1 = ((c0 + 1) & 8) | (((c0 + 1) ^ k7) & 7);
                Bs4[bk][p0] = h0; Bs4[bk][p1] = h1;
                Bs4[bk + 32][p0] = l0; Bs4[bk + 32][p1] = l1;
            }
            __syncthreads();
        }
    }

    // Epilogue: cp[o][n] += bias
#pragma unroll
    for (int mf = 0; mf < 2; mf++) {
        const int o = otile + wm + mf * 16 + g;
        const float b0v = bias[o], b1v = bias[o + 8];
        float* base = g_cp + (size_t)b * CNsz + (size_t)o * Nn + noff + wn + tc * 2;
#pragma unroll
        for (int nf = 0; nf < 8; nf++) {
            *(float2*)(base + nf * 8) =
                make_float2(acc[mf][nf][0] + b0v, acc[mf][nf][1] + b0v);
            *(float2*)(base + nf * 8 + 8 * Nn) =
                make_float2(acc[mf][nf][2] + b1v, acc[mf][nf][3] + b1v);
        }
    }
}

// ============================================================================
// Kernel 2: Mpart[b,h][d,d'] = sum_n cp[b,d*H+h,n] * cross[b,d'*H+h,n]
// One block per (b,h); f32x2 4x4 micro (unchanged from R4).
// ============================================================================
__global__ __launch_bounds__(256) void k_mpart(const float* __restrict__ cross)
{
    __shared__ float As[16][64];
    __shared__ float Bs[16][64];
    const int h = blockIdx.x;
    const int b = blockIdx.y;
    const int tid = threadIdx.x;
    const int r = tid >> 4, c = tid & 15;
    const int lr = tid >> 2, lk = (tid & 3) * 4;

    const float* Ab = g_cp + (size_t)b * CNsz + h * Nn;
    const float* Bp = cross + (size_t)b * CNsz + h * Nn;

    unsigned long long acc[4][2];
#pragma unroll
    for (int i = 0; i < 4; i++) { acc[i][0] = 0ull; acc[i][1] = 0ull; }

    for (int k0 = 0; k0 < Nn; k0 += 16) {
        float4 av = *(const float4*)(Ab + (size_t)lr * HN + k0 + lk);
        float4 bv = *(const float4*)(Bp + (size_t)lr * HN + k0 + lk);
        __syncthreads();
        As[lk + 0][lr] = av.x; As[lk + 1][lr] = av.y;
        As[lk + 2][lr] = av.z; As[lk + 3][lr] = av.w;
        Bs[lk + 0][lr] = bv.x; Bs[lk + 1][lr] = bv.y;
        Bs[lk + 2][lr] = bv.z; Bs[lk + 3][lr] = bv.w;
        __syncthreads();
#pragma unroll
        for (int k = 0; k < 16; k++) {
            float4 ar = *(const float4*)&As[k][r * 4];
            ulonglong2 bp = *(const ulonglong2*)&Bs[k][c * 4];
            unsigned long long s;
            s = splat2(ar.x);
            FMA_F32X2(acc[0][0], s, bp.x, acc[0][0]);
            FMA_F32X2(acc[0][1], s, bp.y, acc[0][1]);
            s = splat2(ar.y);
            FMA_F32X2(acc[1][0], s, bp.x, acc[1][0]);
            FMA_F32X2(acc[1][1], s, bp.y, acc[1][1]);
            s = splat2(ar.z);
            FMA_F32X2(acc[2][0], s, bp.x, acc[2][0]);
            FMA_F32X2(acc[2][1], s, bp.y, acc[2][1]);
            s = splat2(ar.w);
            FMA_F32X2(acc[3][0], s, bp.x, acc[3][0]);
            FMA_F32X2(acc[3][1], s, bp.y, acc[3][1]);
        }
    }

    float* mp = g_Mpart + ((size_t)b * Hh + h) * 4096;
#pragma unroll
    for (int i = 0; i < 4; i++) {
        float2 lo = unpack2(acc[i][0]);
        float2 hi = unpack2(acc[i][1]);
        *(float4*)(mp + (size_t)(r * 4 + i) * 64 + c * 4) =
            make_float4(lo.x, lo.y, hi.x, hi.y);
    }
}

// ============================================================================
// Kernel 3: U[b, m] rows = scale * x-row(m) . M[b]; fused h-reduction of Mpart.
// Grid (96, 4): block = (b, hp) x quarter of d'. Emits bf16 hi/lo planes.
// ============================================================================
__global__ __launch_bounds__(256) void k_out(const float* __restrict__ x_ori)
{
    __shared__ float Ms[64][16];
    const int b = blockIdx.x / Hh;
    const int hp = blockIdx.x % Hh;
    const int q = blockIdx.y;        // d' quarter
    const int tid = threadIdx.x;

    // load + h-reduce the M quarter
    for (int idx = tid; idx < 1024; idx += 256) {
        const int d = idx >> 4, c = idx & 15;
        const float* mp = g_Mpart + ((size_t)b * Hh) * 4096 + d * 64 + q * 16 + c;
        float s = 0.f;
#pragma unroll
        for (int h = 0; h < Hh; h++) s += mp[(size_t)h * 4096];
        Ms[d][c] = s;
    }
    __syncthreads();

    const float* xb = x_ori + (size_t)b * CNsz + hp * Nn + tid;

    float4 acc[4];
#pragma unroll
    for (int e = 0; e < 4; e++) acc[e] = make_float4(0.f, 0.f, 0.f, 0.f);

    for (int d0 = 0; d0 < 64; d0 += 8) {
        float xr[8];
#pragma unroll
        for (int i = 0; i < 8; i++) xr[i] = xb[(size_t)(d0 + i) * HN];
#pragma unroll
        for (int i = 0; i < 8; i++) {
            const float4* Mr = (const float4*)&Ms[d0 + i][0];
            const float xv = xr[i];
#pragma unroll
            for (int e = 0; e < 4; e++) {
                float4 mv = Mr[e];
                acc[e].x += xv * mv.x;
                acc[e].y += xv * mv.y;
                acc[e].z += xv * mv.z;
                acc[e].w += xv * mv.w;
            }
        }
    }

    const int m = hp * Nn + tid;
    const int nf = m / Hh;
    const int hf = m - nf * Hh;
    const size_t off = ((size_t)b * Nn + nf) * Cc + hf * Dd + q * 16;

    float v[16];
    *(float4*)&v[0] = acc[0]; *(float4*)&v[4] = acc[1];
    *(float4*)&v[8] = acc[2]; *(float4*)&v[12] = acc[3];
    uint32_t hw[8], lw[8];
#pragma unroll
    for (int i = 0; i < 8; i++) {
        float f0 = v[2 * i] * SCALE, f1 = v[2 * i + 1] * SCALE;
        __nv_bfloat16 h0 = __float2bfloat16(f0);
        __nv_bfloat16 h1 = __float2bfloat16(f1);
        __nv_bfloat16 l0 = __float2bfloat16(f0 - __bfloat162float(h0));
        __nv_bfloat16 l1 = __float2bfloat16(f1 - __bfloat162float(h1));
        __nv_bfloat162 hh(h0, h1), ll(l0, l1);
        hw[i] = *reinterpret_cast<uint32_t*>(&hh);
        lw[i] = *reinterpret_cast<uint32_t*>(&ll);
    }
    *(uint4*)(g_Uhi + off)     = make_uint4(hw[0], hw[1], hw[2], hw[3]);
    *(uint4*)(g_Uhi + off + 8) = make_uint4(hw[4], hw[5], hw[6], hw[7]);
    *(uint4*)(g_Ulo + off)     = make_uint4(lw[0], lw[1], lw[2], lw[3]);
    *(uint4*)(g_Ulo + off + 8) = make_uint4(lw[4], lw[5], lw[6], lw[7]);
}

// ============================================================================
// Kernel 4: out[b,o,n] = x_ori + b_dep[o] + sum_k U[b,n,k] * W_dep[o,k]
// bf16 3-split tensor core, B operand pre-split by k_out. Grid (16, 6).
// ============================================================================
__global__ __launch_bounds__(256) void k_deproj_mma(
    const float* __restrict__ Wdep, const float* __restrict__ bdep,
    const float* __restrict__ x_ori, float* __restrict__ out)
{
    __shared__ uint4 As4[128][8];   // [o][chunk] hi 0-3 / lo 4-7, swizzled
    __shared__ uint4 Bs4[128][8];   // [n][chunk] hi 0-3 / lo 4-7, swizzled
    const int tid = threadIdx.x;
    const int wid = tid >> 5, lane = tid & 31;
    const int b = blockIdx.x >> 1;
    const int noff = (blockIdx.x & 1) * 128;
    const int otile = blockIdx.y * 128;

    const int wm = (wid >> 1) * 32;
    const int wn = (wid & 1) * 64;
    const int l7 = lane & 7, l15 = lane & 15, lsel = lane >> 4;
    const int ksel = (lane >> 3) & 1;
    const int g = lane >> 2, tc = lane & 3;

    const int am = tid >> 1, akh = (tid & 1) * 16;   // A staging
    const int un = tid >> 1, ukh = (tid & 1) * 16;   // B staging (U rows)

    const float* Agp = Wdep + (size_t)(otile + am) * Cc + akh;
    const __nv_bfloat16* Uhp = g_Uhi + ((size_t)b * Nn + noff + un) * Cc + ukh;
    const __nv_bfloat16* Ulp = g_Ulo + ((size_t)b * Nn + noff + un) * Cc + ukh;

    const uint32_t as_base = smem_u32(&As4[0][0]);
    const uint32_t bs_base = smem_u32(&Bs4[0][0]);
    const int rowA = wm + l15;
    const int rowNl = (lane & 7) + (lsel << 3);   // lane's n-row within 16

    float acc[2][8][4];
#pragma unroll
    for (int i = 0; i < 2; i++)
#pragma unroll
        for (int j = 0; j < 8; j++)
#pragma unroll
            for (int e = 0; e < 4; e++) acc[i][j][e] = 0.f;

    float4 pa[4];
    uint4 uh[2], ul[2];
#pragma unroll
    for (int i = 0; i < 4; i++) pa[i] = *(const float4*)(Agp + i * 4);
    uh[0] = *(const uint4*)(Uhp); uh[1] = *(const uint4*)(Uhp + 8);
    ul[0] = *(const uint4*)(Ulp); ul[1] = *(const uint4*)(Ulp + 8);

    {
        stage_A(&As4[0][0], am, akh, pa);
        const int c0 = ukh >> 3, n7 = un & 7;
        uint4* row = &Bs4[un][0];
        row[(c0 + 0) ^ n7] = uh[0];
        row[(c0 + 1) ^ n7] = uh[1];
        row[(c0 + 4) ^ n7] = ul[0];
        row[(c0 + 5) ^ n7] = ul[1];
    }
    __syncthreads();

    for (int kt = 0; kt < GNT; kt++) {
        if (kt + 1 < GNT) {
            Agp += 32; Uhp += 32; Ulp += 32;
#pragma unroll
            for (int i = 0; i < 4; i++) pa[i] = *(const float4*)(Agp + i * 4);
            uh[0] = *(const uint4*)(Uhp); uh[1] = *(const uint4*)(Uhp + 8);
            ul[0] = *(const uint4*)(Ulp); ul[1] = *(const uint4*)(Ulp + 8);
        }
#pragma unroll
        for (int ks = 0; ks < 2; ks++) {
            const int k0 = ks * 16;
            uint32_t a_h[2][4], a_l[2][4];
#pragma unroll
            for (int mf = 0; mf < 2; mf++) {
                const uint32_t rbase = as_base + (uint32_t)(rowA + mf * 16) * 128;
                const int ch = ((k0 >> 3) + lsel) ^ l7;
                const int cl = ((k0 >> 3) + lsel + 4) ^ l7;
                LDSM_X4(a_h[mf][0], a_h[mf][1], a_h[mf][2], a_h[mf][3], rbase + ch * 16);
                LDSM_X4(a_l[mf][0], a_l[mf][1], a_l[mf][2], a_l[mf][3], rbase + cl * 16);
            }
#pragma unroll
            for (int np = 0; np < 4; np++) {
                const int rowN = wn + np * 16 + rowNl;
                const uint32_t rb = bs_base + (uint32_t)rowN * 128;
                const int ch = ((k0 >> 3) + ksel) ^ l7;
                const int cl = ((k0 >> 3) + ksel + 4) ^ l7;
                uint32_t bh[4], bl[4];
                LDSM_X4(bh[0], bh[1], bh[2], bh[3], rb + ch * 16);
                LDSM_X4(bl[0], bl[1], bl[2], bl[3], rb + cl * 16);
#pragma unroll
                for (int mf = 0; mf < 2; mf++) {
                    MMA_BF16(acc[mf][2 * np], a_h[mf][0], a_h[mf][1], a_h[mf][2], a_h[mf][3], bh[0], bh[1]);
                    MMA_BF16(acc[mf][2 * np], a_l[mf][0], a_l[mf][1], a_l[mf][2], a_l[mf][3], bh[0], bh[1]);
                    MMA_BF16(acc[mf][2 * np], a_h[mf][0], a_h[mf][1], a_h[mf][2], a_h[mf][3], bl[0], bl[1]);
                    MMA_BF16(acc[mf][2 * np + 1], a_h[mf][0], a_h[mf][1], a_h[mf][2], a_h[mf][3], bh[2], bh[3]);
                    MMA_BF16(acc[mf][2 * np + 1], a_l[mf][0], a_l[mf][1], a_l[mf][2], a_l[mf][3], bh[2], bh[3]);
                    MMA_BF16(acc[mf][2 * np + 1], a_h[mf][0], a_h[mf][1], a_h[mf][2], a_h[mf][3], bl[2], bl[3]);
                }
            }
        }
        if (kt + 1 < GNT) {
            __syncthreads();
            stage_A(&As4[0][0], am, akh, pa);
            const int c0 = ukh >> 3, n7 = un & 7;
            uint4* row = &Bs4[un][0];
            row[(c0 + 0) ^ n7] = uh[0];
            row[(c0 + 1) ^ n7] = uh[1];
            row[(c0 + 4) ^ n7] = ul[0];
            row[(c0 + 5) ^ n7] = ul[1];
            __syncthreads();
        }
    }

    // Epilogue: + bias + skip, write out
#pragma unroll
    for (int mf = 0; mf < 2; mf++) {
        const int o = otile + wm + mf * 16 + g;
        const float b0v = bdep[o], b1v = bdep[o + 8];
        const size_t base = (size_t)b * CNsz + (size_t)o * Nn + noff + wn + tc * 2;
#pragma unroll
        for (int nf = 0; nf < 8; nf++) {
            const size_t i0 = base + nf * 8;
            float2 x0 = *(const float2*)(x_ori + i0);
            float2 x1 = *(const float2*)(x_ori + i0 + 8 * Nn);
            *(float2*)(out + i0) =
                make_float2(acc[mf][nf][0] + b0v + x0.x, acc[mf][nf][1] + b0v + x0.y);
            *(float2*)(out + i0 + 8 * Nn) =
                make_float2(acc[mf][nf][2] + b1v + x1.x, acc[mf][nf][3] + b1v + x1.y);
        }
    }
}

// ============================================================================
// Launch
// ============================================================================
extern "C" void kernel_launch(void* const* d_in, const int* in_sizes, int n_in,
                              void* d_out, int out_size)
{
    (void)in_sizes; (void)n_in; (void)out_size;
    const float* x_ori  = (const float*)d_in[0];
    const float* cross  = (const float*)d_in[1];
    const float* W_proj = (const float*)d_in[2];
    const float* b_proj = (const float*)d_in[3];
    const float* W_dep  = (const float*)d_in[4];
    const float* b_dep  = (const float*)d_in[5];
    float* out = (float*)d_out;

    k_proj_mma<<<dim3(16, 6), 256>>>(W_proj, cross, b_proj);
    k_mpart<<<dim3(Hh, Bb), 256>>>(cross);
    k_out<<<dim3(Bb * Hh, 4), 256>>>(x_ori);
    k_deproj_mma<<<dim3(16, 6), 256>>>(W_dep, b_dep, x_ori, out);
}

// round 7
// speedup vs baseline: 3.9703x; 1.0585x over previous
#include <cuda_runtime.h>
#include <cuda_bf16.h>
#include <cstdint>

// Problem constants
#define Bb   8
#define Cc   768
#define Nn   256
#define Hh   12
#define Dd   64
#define HN   3072          // Hh*Nn
#define CNsz 196608        // Cc*Nn
#define SCALE 0.125f       // D^-0.5
#define GNT  24            // K tiles of 32 (K = 768)

// Scratch (allocation-free: __device__ globals)
__device__ float g_cp[Bb * CNsz];                 // proj(cross): [B, C, N] fp32
__device__ float g_Mpart[Bb * Hh * Dd * Dd];      // per-(b,h) partial 64x64
__device__ __nv_bfloat16 g_Uhi[Bb * Nn * Cc];     // U hi plane [B, N, C]
__device__ __nv_bfloat16 g_Ulo[Bb * Nn * Cc];     // U lo plane [B, N, C]

// ---- packed f32x2 helpers (for k_mpart) ----
#define FMA_F32X2(d, a, b, c) \
    asm("fma.rn.f32x2 %0, %1, %2, %3;" : "=l"(d) : "l"(a), "l"(b), "l"(c))

static __device__ __forceinline__ unsigned long long splat2(float x) {
    unsigned long long r;
    unsigned u = __float_as_uint(x);
    asm("mov.b64 %0, {%1, %1};" : "=l"(r) : "r"(u));
    return r;
}
static __device__ __forceinline__ float2 unpack2(unsigned long long v) {
    unsigned lo, hi;
    asm("mov.b64 {%0, %1}, %2;" : "=r"(lo), "=r"(hi) : "l"(v));
    return make_float2(__uint_as_float(lo), __uint_as_float(hi));
}

// ---- tensor-core primitives ----
static __device__ __forceinline__ uint32_t smem_u32(const void* p) {
    return (uint32_t)__cvta_generic_to_shared(p);
}

#define LDSM_X4(r0, r1, r2, r3, addr) \
    asm volatile("ldmatrix.sync.aligned.m8n8.x4.shared.b16 {%0,%1,%2,%3}, [%4];" \
        : "=r"(r0), "=r"(r1), "=r"(r2), "=r"(r3) : "r"(addr))

#define LDSM_X4_T(r0, r1, r2, r3, addr) \
    asm volatile("ldmatrix.sync.aligned.m8n8.x4.trans.shared.b16 {%0,%1,%2,%3}, [%4];" \
        : "=r"(r0), "=r"(r1), "=r"(r2), "=r"(r3) : "r"(addr))

#define MMA_BF16(D, a0, a1, a2, a3, b0, b1) \
    asm volatile("mma.sync.aligned.m16n8k16.row.col.f32.bf16.bf16.f32 " \
        "{%0,%1,%2,%3}, {%4,%5,%6,%7}, {%8,%9}, {%0,%1,%2,%3};" \
        : "+f"((D)[0]), "+f"((D)[1]), "+f"((D)[2]), "+f"((D)[3]) \
        : "r"(a0), "r"(a1), "r"(a2), "r"(a3), "r"(b0), "r"(b1))

// Split 8 fp32 -> bf16 hi chunk (16B) + bf16 lo chunk (16B)
static __device__ __forceinline__ void split8(float4 u, float4 v, uint4& hi, uint4& lo) {
    float f[8] = {u.x, u.y, u.z, u.w, v.x, v.y, v.z, v.w};
    uint32_t hw[4], lw[4];
#pragma unroll
    for (int i = 0; i < 4; i++) {
        __nv_bfloat16 h0 = __float2bfloat16(f[2 * i]);
        __nv_bfloat16 h1 = __float2bfloat16(f[2 * i + 1]);
        __nv_bfloat16 l0 = __float2bfloat16(f[2 * i] - __bfloat162float(h0));
        __nv_bfloat16 l1 = __float2bfloat16(f[2 * i + 1] - __bfloat162float(h1));
        __nv_bfloat162 hh(h0, h1), ll(l0, l1);
        hw[i] = *reinterpret_cast<uint32_t*>(&hh);
        lw[i] = *reinterpret_cast<uint32_t*>(&ll);
    }
    hi = make_uint4(hw[0], hw[1], hw[2], hw[3]);
    lo = make_uint4(lw[0], lw[1], lw[2], lw[3]);
}

// ============================================================================
// Kernel 1: cp = W_proj @ cross + b_proj, bf16 3-split tensor core.
// Block tile 128(o) x 64(n), BK=32, double-buffered smem, 1 barrier/tile.
// Grid (32, 6) = 192 blocks; 2 blocks/SM via launch_bounds(256,2).
// ============================================================================
__global__ __launch_bounds__(256, 2) void k_proj_mma(
    const float* __restrict__ W, const float* __restrict__ cross,
    const float* __restrict__ bias)
{
    __shared__ uint4 As4[2][128][8];   // [buf][m][chunk 0-3 hi / 4-7 lo], XOR swizzle
    __shared__ uint4 Bs4[2][64][8];    // [buf][k 0-31 hi / 32-63 lo][n chunk]
    const int tid = threadIdx.x;
    const int wid = tid >> 5, lane = tid & 31;
    const int b = blockIdx.x >> 2;
    const int noff = (blockIdx.x & 3) * 64;
    const int otile = blockIdx.y * 128;

    const int wm = (wid >> 1) * 32;   // 0,32,64,96
    const int wn = (wid & 1) * 32;    // 0,32
    const int l7 = lane & 7, l15 = lane & 15, lsel = lane >> 4;
    const int g = lane >> 2, tc = lane & 3;

    // staging indices
    const int arow = tid >> 2, akseg = tid & 3;    // A rows arow, arow+64
    const int am7 = arow & 7;
    const int bkrow = tid >> 3, bnseg = tid & 7;   // B k-row, n chunk
    const int bk7 = bkrow & 7;

    const float* Agp = W + (size_t)(otile + arow) * Cc + akseg * 8;
    const float* Bgp = cross + (size_t)b * CNsz + (size_t)bkrow * Nn + noff + bnseg * 8;

    const uint32_t as_base = smem_u32(&As4[0][0][0]);
    const uint32_t bs_base = smem_u32(&Bs4[0][0][0]);

    float acc[2][4][4];
#pragma unroll
    for (int i = 0; i < 2; i++)
#pragma unroll
        for (int j = 0; j < 4; j++)
#pragma unroll
            for (int e = 0; e < 4; e++) acc[i][j][e] = 0.f;

    float4 a0[2], a1[2], bv[2];
    a0[0] = *(const float4*)(Agp);
    a0[1] = *(const float4*)(Agp + 4);
    a1[0] = *(const float4*)(Agp + (size_t)64 * Cc);
    a1[1] = *(const float4*)(Agp + (size_t)64 * Cc + 4);
    bv[0] = *(const float4*)(Bgp);
    bv[1] = *(const float4*)(Bgp + 4);

    {
        uint4 h, l;
        split8(a0[0], a0[1], h, l);
        As4[0][arow][akseg ^ am7] = h;
        As4[0][arow][(akseg + 4) ^ am7] = l;
        split8(a1[0], a1[1], h, l);
        As4[0][arow + 64][akseg ^ am7] = h;
        As4[0][arow + 64][(akseg + 4) ^ am7] = l;
        split8(bv[0], bv[1], h, l);
        Bs4[0][bkrow][bnseg ^ bk7] = h;
        Bs4[0][bkrow + 32][bnseg ^ bk7] = l;
    }
    __syncthreads();

    for (int kt = 0; kt < GNT; kt++) {
        const int cur = kt & 1;
        if (kt + 1 < GNT) {
            Agp += 32;
            Bgp += (size_t)32 * Nn;
            a0[0] = *(const float4*)(Agp);
            a0[1] = *(const float4*)(Agp + 4);
            a1[0] = *(const float4*)(Agp + (size_t)64 * Cc);
            a1[1] = *(const float4*)(Agp + (size_t)64 * Cc + 4);
            bv[0] = *(const float4*)(Bgp);
            bv[1] = *(const float4*)(Bgp + 4);
        }

        const uint32_t asb = as_base + (uint32_t)cur * 16384;
        const uint32_t bsb = bs_base + (uint32_t)cur * 8192;
#pragma unroll
        for (int ks = 0; ks < 2; ks++) {
            const int k0 = ks * 16;
            uint32_t ah[2][4], al[2][4];
#pragma unroll
            for (int mf = 0; mf < 2; mf++) {
                const uint32_t rbase = asb + (uint32_t)(wm + mf * 16 + l15) * 128;
                const int ch = ((k0 >> 3) + lsel) ^ l7;
                const int cl = ((k0 >> 3) + lsel + 4) ^ l7;
                LDSM_X4(ah[mf][0], ah[mf][1], ah[mf][2], ah[mf][3], rbase + ch * 16);
                LDSM_X4(al[mf][0], al[mf][1], al[mf][2], al[mf][3], rbase + cl * 16);
            }
#pragma unroll
            for (int np = 0; np < 2; np++) {
                const int c = (wn >> 3) + np * 2 + lsel;
                const int p = c ^ l7;
                const uint32_t rb = bsb + (uint32_t)(k0 + l15) * 128 + p * 16;
                uint32_t bh[4], bl[4];
                LDSM_X4_T(bh[0], bh[1], bh[2], bh[3], rb);
                LDSM_X4_T(bl[0], bl[1], bl[2], bl[3], rb + 32 * 128);
#pragma unroll
                for (int mf = 0; mf < 2; mf++) {
                    MMA_BF16(acc[mf][2 * np], ah[mf][0], ah[mf][1], ah[mf][2], ah[mf][3], bh[0], bh[1]);
                    MMA_BF16(acc[mf][2 * np], al[mf][0], al[mf][1], al[mf][2], al[mf][3], bh[0], bh[1]);
                    MMA_BF16(acc[mf][2 * np], ah[mf][0], ah[mf][1], ah[mf][2], ah[mf][3], bl[0], bl[1]);
                    MMA_BF16(acc[mf][2 * np + 1], ah[mf][0], ah[mf][1], ah[mf][2], ah[mf][3], bh[2], bh[3]);
                    MMA_BF16(acc[mf][2 * np + 1], al[mf][0], al[mf][1], al[mf][2], al[mf][3], bh[2], bh[3]);
                    MMA_BF16(acc[mf][2 * np + 1], ah[mf][0], ah[mf][1], ah[mf][2], ah[mf][3], bl[2], bl[3]);
                }
            }
        }

        if (kt + 1 < GNT) {
            const int nxt = cur ^ 1;
            uint4 h, l;
            split8(a0[0], a0[1], h, l);
            As4[nxt][arow][akseg ^ am7] = h;
            As4[nxt][arow][(akseg + 4) ^ am7] = l;
            split8(a1[0], a1[1], h, l);
            As4[nxt][arow + 64][akseg ^ am7] = h;
            As4[nxt][arow + 64][(akseg + 4) ^ am7] = l;
            split8(bv[0], bv[1], h, l);
            Bs4[nxt][bkrow][bnseg ^ bk7] = h;
            Bs4[nxt][bkrow + 32][bnseg ^ bk7] = l;
            __syncthreads();
        }
    }

    // Epilogue: cp[o][n] + bias
#pragma unroll
    for (int mf = 0; mf < 2; mf++) {
        const int o = otile + wm + mf * 16 + g;
        const float b0v = bias[o], b1v = bias[o + 8];
        float* base = g_cp + (size_t)b * CNsz + (size_t)o * Nn + noff + wn + tc * 2;
#pragma unroll
        for (int nf = 0; nf < 4; nf++) {
            *(float2*)(base + nf * 8) =
                make_float2(acc[mf][nf][0] + b0v, acc[mf][nf][1] + b0v);
            *(float2*)(base + nf * 8 + 8 * Nn) =
                make_float2(acc[mf][nf][2] + b1v, acc[mf][nf][3] + b1v);
        }
    }
}

// ============================================================================
// Kernel 2: Mpart[b,h][d,d'] = sum_n cp[b,d*H+h,n] * cross[b,d'*H+h,n]
// One block per (b,h); f32x2 4x4 micro.
// ============================================================================
__global__ __launch_bounds__(256) void k_mpart(const float* __restrict__ cross)
{
    __shared__ float As[16][64];
    __shared__ float Bs[16][64];
    const int h = blockIdx.x;
    const int b = blockIdx.y;
    const int tid = threadIdx.x;
    const int r = tid >> 4, c = tid & 15;
    const int lr = tid >> 2, lk = (tid & 3) * 4;

    const float* Ab = g_cp + (size_t)b * CNsz + h * Nn;
    const float* Bp = cross + (size_t)b * CNsz + h * Nn;

    unsigned long long acc[4][2];
#pragma unroll
    for (int i = 0; i < 4; i++) { acc[i][0] = 0ull; acc[i][1] = 0ull; }

    for (int k0 = 0; k0 < Nn; k0 += 16) {
        float4 av = *(const float4*)(Ab + (size_t)lr * HN + k0 + lk);
        float4 bv = *(const float4*)(Bp + (size_t)lr * HN + k0 + lk);
        __syncthreads();
        As[lk + 0][lr] = av.x; As[lk + 1][lr] = av.y;
        As[lk + 2][lr] = av.z; As[lk + 3][lr] = av.w;
        Bs[lk + 0][lr] = bv.x; Bs[lk + 1][lr] = bv.y;
        Bs[lk + 2][lr] = bv.z; Bs[lk + 3][lr] = bv.w;
        __syncthreads();
#pragma unroll
        for (int k = 0; k < 16; k++) {
            float4 ar = *(const float4*)&As[k][r * 4];
            ulonglong2 bp = *(const ulonglong2*)&Bs[k][c * 4];
            unsigned long long s;
            s = splat2(ar.x);
            FMA_F32X2(acc[0][0], s, bp.x, acc[0][0]);
            FMA_F32X2(acc[0][1], s, bp.y, acc[0][1]);
            s = splat2(ar.y);
            FMA_F32X2(acc[1][0], s, bp.x, acc[1][0]);
            FMA_F32X2(acc[1][1], s, bp.y, acc[1][1]);
            s = splat2(ar.z);
            FMA_F32X2(acc[2][0], s, bp.x, acc[2][0]);
            FMA_F32X2(acc[2][1], s, bp.y, acc[2][1]);
            s = splat2(ar.w);
            FMA_F32X2(acc[3][0], s, bp.x, acc[3][0]);
            FMA_F32X2(acc[3][1], s, bp.y, acc[3][1]);
        }
    }

    float* mp = g_Mpart + ((size_t)b * Hh + h) * 4096;
#pragma unroll
    for (int i = 0; i < 4; i++) {
        float2 lo = unpack2(acc[i][0]);
        float2 hi = unpack2(acc[i][1]);
        *(float4*)(mp + (size_t)(r * 4 + i) * 64 + c * 4) =
            make_float4(lo.x, lo.y, hi.x, hi.y);
    }
}

// ============================================================================
// Kernel 3: U rows = scale * x-row(m) . M[b]; fused h-reduction of Mpart.
// Grid (96, 4); emits bf16 hi/lo planes for the deproj tensor-core GEMM.
// ============================================================================
__global__ __launch_bounds__(256) void k_out(const float* __restrict__ x_ori)
{
    __shared__ float Ms[64][16];
    const int b = blockIdx.x / Hh;
    const int hp = blockIdx.x % Hh;
    const int q = blockIdx.y;        // d' quarter
    const int tid = threadIdx.x;

    for (int idx = tid; idx < 1024; idx += 256) {
        const int d = idx >> 4, c = idx & 15;
        const float* mp = g_Mpart + ((size_t)b * Hh) * 4096 + d * 64 + q * 16 + c;
        float s = 0.f;
#pragma unroll
        for (int h = 0; h < Hh; h++) s += mp[(size_t)h * 4096];
        Ms[d][c] = s;
    }
    __syncthreads();

    const float* xb = x_ori + (size_t)b * CNsz + hp * Nn + tid;

    float4 acc[4];
#pragma unroll
    for (int e = 0; e < 4; e++) acc[e] = make_float4(0.f, 0.f, 0.f, 0.f);

    for (int d0 = 0; d0 < 64; d0 += 8) {
        float xr[8];
#pragma unroll
        for (int i = 0; i < 8; i++) xr[i] = xb[(size_t)(d0 + i) * HN];
#pragma unroll
        for (int i = 0; i < 8; i++) {
            const float4* Mr = (const float4*)&Ms[d0 + i][0];
            const float xv = xr[i];
#pragma unroll
            for (int e = 0; e < 4; e++) {
                float4 mv = Mr[e];
                acc[e].x += xv * mv.x;
                acc[e].y += xv * mv.y;
                acc[e].z += xv * mv.z;
                acc[e].w += xv * mv.w;
            }
        }
    }

    const int m = hp * Nn + tid;
    const int nf = m / Hh;
    const int hf = m - nf * Hh;
    const size_t off = ((size_t)b * Nn + nf) * Cc + hf * Dd + q * 16;

    float v[16];
    *(float4*)&v[0] = acc[0]; *(float4*)&v[4] = acc[1];
    *(float4*)&v[8] = acc[2]; *(float4*)&v[12] = acc[3];
    uint32_t hw[8], lw[8];
#pragma unroll
    for (int i = 0; i < 8; i++) {
        float f0 = v[2 * i] * SCALE, f1 = v[2 * i + 1] * SCALE;
        __nv_bfloat16 h0 = __float2bfloat16(f0);
        __nv_bfloat16 h1 = __float2bfloat16(f1);
        __nv_bfloat16 l0 = __float2bfloat16(f0 - __bfloat162float(h0));
        __nv_bfloat16 l1 = __float2bfloat16(f1 - __bfloat162float(h1));
        __nv_bfloat162 hh(h0, h1), ll(l0, l1);
        hw[i] = *reinterpret_cast<uint32_t*>(&hh);
        lw[i] = *reinterpret_cast<uint32_t*>(&ll);
    }
    *(uint4*)(g_Uhi + off)     = make_uint4(hw[0], hw[1], hw[2], hw[3]);
    *(uint4*)(g_Uhi + off + 8) = make_uint4(hw[4], hw[5], hw[6], hw[7]);
    *(uint4*)(g_Ulo + off)     = make_uint4(lw[0], lw[1], lw[2], lw[3]);
    *(uint4*)(g_Ulo + off + 8) = make_uint4(lw[4], lw[5], lw[6], lw[7]);
}

// ============================================================================
// Kernel 4: out = x_ori + b_dep + U @ W_dep^T (transposed write), bf16 3-split.
// Same 128x64 double-buffered skeleton; B operand pre-split bf16 from k_out.
// ============================================================================
__global__ __launch_bounds__(256, 2) void k_deproj_mma(
    const float* __restrict__ Wdep, const float* __restrict__ bdep,
    const float* __restrict__ x_ori, float* __restrict__ out)
{
    __shared__ uint4 As4[2][128][8];   // [buf][o][chunk hi 0-3 / lo 4-7]
    __shared__ uint4 Bs4[2][64][8];    // [buf][n][chunk hi 0-3 / lo 4-7]
    const int tid = threadIdx.x;
    const int wid = tid >> 5, lane = tid & 31;
    const int b = blockIdx.x >> 2;
    const int noff = (blockIdx.x & 3) * 64;
    const int otile = blockIdx.y * 128;

    const int wm = (wid >> 1) * 32;
    const int wn = (wid & 1) * 32;
    const int l7 = lane & 7, l15 = lane & 15, lsel = lane >> 4;
    const int ksel = (lane >> 3) & 1;
    const int rowNl = (lane & 7) + (lsel << 3);
    const int g = lane >> 2, tc = lane & 3;

    const int arow = tid >> 2, akseg = tid & 3;
    const int am7 = arow & 7;
    const int bnrow = tid >> 3, bc = tid & 7;      // B: n-rows bnrow, bnrow+32
    const int bn7 = bnrow & 7;

    const float* Agp = Wdep + (size_t)(otile + arow) * Cc + akseg * 8;
    const __nv_bfloat16* Usrc = (bc < 4) ? g_Uhi : g_Ulo;
    const __nv_bfloat16* Ugp =
        Usrc + ((size_t)b * Nn + noff + bnrow) * Cc + (bc & 3) * 8;

    const uint32_t as_base = smem_u32(&As4[0][0][0]);
    const uint32_t bs_base = smem_u32(&Bs4[0][0][0]);

    float acc[2][4][4];
#pragma unroll
    for (int i = 0; i < 2; i++)
#pragma unroll
        for (int j = 0; j < 4; j++)
#pragma unroll
            for (int e = 0; e < 4; e++) acc[i][j][e] = 0.f;

    float4 a0[2], a1[2];
    uint4 u0, u1;
    a0[0] = *(const float4*)(Agp);
    a0[1] = *(const float4*)(Agp + 4);
    a1[0] = *(const float4*)(Agp + (size_t)64 * Cc);
    a1[1] = *(const float4*)(Agp + (size_t)64 * Cc + 4);
    u0 = *(const uint4*)(Ugp);
    u1 = *(const uint4*)(Ugp + (size_t)32 * Cc);

    {
        uint4 h, l;
        split8(a0[0], a0[1], h, l);
        As4[0][arow][akseg ^ am7] = h;
        As4[0][arow][(akseg + 4) ^ am7] = l;
        split8(a1[0], a1[1], h, l);
        As4[0][arow + 64][akseg ^ am7] = h;
        As4[0][arow + 64][(akseg + 4) ^ am7] = l;
        Bs4[0][bnrow][bc ^ bn7] = u0;
        Bs4[0][bnrow + 32][bc ^ bn7] = u1;
    }
    __syncthreads();

    for (int kt = 0; kt < GNT; kt++) {
        const int cur = kt & 1;
        if (kt + 1 < GNT) {
            Agp += 32;
            Ugp += 32;
            a0[0] = *(const float4*)(Agp);
            a0[1] = *(const float4*)(Agp + 4);
            a1[0] = *(const float4*)(Agp + (size_t)64 * Cc);
            a1[1] = *(const float4*)(Agp + (size_t)64 * Cc + 4);
            u0 = *(const uint4*)(Ugp);
            u1 = *(const uint4*)(Ugp + (size_t)32 * Cc);
        }

        const uint32_t asb = as_base + (uint32_t)cur * 16384;
        const uint32_t bsb = bs_base + (uint32_t)cur * 8192;
#pragma unroll
        for (int ks = 0; ks < 2; ks++) {
            const int k0 = ks * 16;
            uint32_t ah[2][4], al[2][4];
#pragma unroll
            for (int mf = 0; mf < 2; mf++) {
                const uint32_t rbase = asb + (uint32_t)(wm + mf * 16 + l15) * 128;
                const int ch = ((k0 >> 3) + lsel) ^ l7;
                const int cl = ((k0 >> 3) + lsel + 4) ^ l7;
                LDSM_X4(ah[mf][0], ah[mf][1], ah[mf][2], ah[mf][3], rbase + ch * 16);
                LDSM_X4(al[mf][0], al[mf][1], al[mf][2], al[mf][3], rbase + cl * 16);
            }
#pragma unroll
            for (int np = 0; np < 2; np++) {
                const int rowN = wn + np * 16 + rowNl;
                const int ch = ((k0 >> 3) + ksel) ^ l7;
                const int cl = ((k0 >> 3) + ksel + 4) ^ l7;
                const uint32_t rb = bsb + (uint32_t)rowN * 128;
                uint32_t bh[4], bl[4];
                LDSM_X4(bh[0], bh[1], bh[2], bh[3], rb + ch * 16);
                LDSM_X4(bl[0], bl[1], bl[2], bl[3], rb + cl * 16);
#pragma unroll
                for (int mf = 0; mf < 2; mf++) {
                    MMA_BF16(acc[mf][2 * np], ah[mf][0], ah[mf][1], ah[mf][2], ah[mf][3], bh[0], bh[1]);
                    MMA_BF16(acc[mf][2 * np], al[mf][0], al[mf][1], al[mf][2], al[mf][3], bh[0], bh[1]);
                    MMA_BF16(acc[mf][2 * np], ah[mf][0], ah[mf][1], ah[mf][2], ah[mf][3], bl[0], bl[1]);
                    MMA_BF16(acc[mf][2 * np + 1], ah[mf][0], ah[mf][1], ah[mf][2], ah[mf][3], bh[2], bh[3]);
                    MMA_BF16(acc[mf][2 * np + 1], al[mf][0], al[mf][1], al[mf][2], al[mf][3], bh[2], bh[3]);
                    MMA_BF16(acc[mf][2 * np + 1], ah[mf][0], ah[mf][1], ah[mf][2], ah[mf][3], bl[2], bl[3]);
                }
            }
        }

        if (kt + 1 < GNT) {
            const int nxt = cur ^ 1;
            uint4 h, l;
            split8(a0[0], a0[1], h, l);
            As4[nxt][arow][akseg ^ am7] = h;
            As4[nxt][arow][(akseg + 4) ^ am7] = l;
            split8(a1[0], a1[1], h, l);
            As4[nxt][arow + 64][akseg ^ am7] = h;
            As4[nxt][arow + 64][(akseg + 4) ^ am7] = l;
            Bs4[nxt][bnrow][bc ^ bn7] = u0;
            Bs4[nxt][bnrow + 32][bc ^ bn7] = u1;
            __syncthreads();
        }
    }

    // Epilogue: + bias + skip
#pragma unroll
    for (int mf = 0; mf < 2; mf++) {
        const int o = otile + wm + mf * 16 + g;
        const float b0v = bdep[o], b1v = bdep[o + 8];
        const size_t base = (size_t)b * CNsz + (size_t)o * Nn + noff + wn + tc * 2;
#pragma unroll
        for (int nf = 0; nf < 4; nf++) {
            const size_t i0 = base + nf * 8;
            float2 x0 = *(const float2*)(x_ori + i0);
            float2 x1 = *(const float2*)(x_ori + i0 + 8 * Nn);
            *(float2*)(out + i0) =
                make_float2(acc[mf][nf][0] + b0v + x0.x, acc[mf][nf][1] + b0v + x0.y);
            *(float2*)(out + i0 + 8 * Nn) =
                make_float2(acc[mf][nf][2] + b1v + x1.x, acc[mf][nf][3] + b1v + x1.y);
        }
    }
}

// ============================================================================
// Launch
// ============================================================================
extern "C" void kernel_launch(void* const* d_in, const int* in_sizes, int n_in,
                              void* d_out, int out_size)
{
    (void)in_sizes; (void)n_in; (void)out_size;
    const float* x_ori  = (const float*)d_in[0];
    const float* cross  = (const float*)d_in[1];
    const float* W_proj = (const float*)d_in[2];
    const float* b_proj = (const float*)d_in[3];
    const float* W_dep  = (const float*)d_in[4];
    const float* b_dep  = (const float*)d_in[5];
    float* out = (float*)d_out;

    k_proj_mma<<<dim3(32, 6), 256>>>(W_proj, cross, b_proj);
    k_mpart<<<dim3(Hh, Bb), 256>>>(cross);
    k_out<<<dim3(Bb * Hh, 4), 256>>>(x_ori);
    k_deproj_mma<<<dim3(32, 6), 256>>>(W_dep, b_dep, x_ori, out);
}